// round 10
// baseline (speedup 1.0000x reference)
#include <cuda_runtime.h>
#include <cstddef>

// ============================================================================
// CommNetActor — algebraically collapsed + f32x2 packed FMA + MUFU-free sigmoid.
//
//   H0 = sigmoid(O @ W_enc + b_enc)                      [B, A, 64]
//   4 comm layers (all LINEAR) + decoder compose into:
//   out[b] = H0[b].flatten() @ M + const                 M: [4096, 32]
//
// Comm layer: H' = H (Wt - Wb/64) + (1/64) J H Wb + 1 b^T    (J = ones(64,64))
// Closure:    E' = E We ; F' = F(We+Wb) + E Wb ; g' = (We+Wb)^T g + b
// Decoder:    M[(a,k),n] = (E Wdec_a)[k][n] + (1/64 F Wsum)[k][n]
//             const = Wsum^T g + b_dec,  Wsum = sum_a Wdec_a
//
// Perf model: prior kernel was MUFU-bound (67M MUFU = ~500us). This version:
//  - sigmoid with zero MUFU (poly exp2 + Newton rcp)
//  - fma.rn.f32x2 (FFMA2) pairing the K dimension -> 2x FMA throughput,
//    no pack ops (W stored transposed; M stored transposed)
// ============================================================================

#define TPB 256
#define BPC 4
#define NBATCH 8192

typedef unsigned long long u64;

__device__ float gE[64 * 64];
__device__ float gT[64 * 32];
__device__ float gConst[32];
__device__ float gWsum[64 * 32];
__device__ float gMT[32 * 4096];     // M transposed: [n][a*64+k]

// ---------------------------------------------------------------------------
__device__ __forceinline__ void ffma2(u64& d, u64 a, u64 b) {
    asm("fma.rn.f32x2 %0, %1, %2, %0;" : "+l"(d) : "l"(a), "l"(b));
}
__device__ __forceinline__ u64 add2(u64 a, u64 b) {
    u64 d; asm("add.rn.f32x2 %0, %1, %2;" : "=l"(d) : "l"(a), "l"(b)); return d;
}
__device__ __forceinline__ float unpack_sum(u64 v) {
    float lo, hi;
    asm("mov.b64 {%0, %1}, %2;" : "=f"(lo), "=f"(hi) : "l"(v));
    return lo + hi;
}

// MUFU-free sigmoid: 1/(1+2^(-x*log2e)). ~18 FMA/ALU ops, rel err ~3e-6.
__device__ __forceinline__ float fast_sigmoid(float x) {
    float t = x * -1.44269504088896f;
    t = fminf(fmaxf(t, -126.0f), 126.0f);
    float fi = t + 12582912.0f;                       // 1.5*2^23 magic round
    int   ib = __float_as_int(fi) - 0x4B400000;       // = rint(t)
    float f  = t - (fi - 12582912.0f);                // f in [-0.5, 0.5]
    float p  = 1.3333558e-3f;                         // 2^f Taylor/minimax deg-5
    p = fmaf(p, f, 9.6181291e-3f);
    p = fmaf(p, f, 5.5504109e-2f);
    p = fmaf(p, f, 2.4022651e-1f);
    p = fmaf(p, f, 6.9314718e-1f);
    p = fmaf(p, f, 1.0f);
    float e = __int_as_float(__float_as_int(p) + (int)((unsigned)ib << 23));
    float d = 1.0f + e;
    float r = __int_as_float(0x7EF311C3 - __float_as_int(d));   // rcp seed
    r = r * (2.0f - d * r);
    r = r * (2.0f - d * r);
    return r;
}

// ---------------------------------------------------------------------------
// P0: Wsum[d][n] = sum_a Wdec[(a*64+d)][n]. Parallel (was DRAM-latency bound
// inside single-CTA p1).
// ---------------------------------------------------------------------------
__global__ void p0_wsum(const float* __restrict__ Wdec)
{
    int idx = blockIdx.x * 256 + threadIdx.x;   // 0..2047
    float s = 0.0f;
#pragma unroll 8
    for (int a = 0; a < 64; a++) s += Wdec[a * 2048 + idx];
    gWsum[idx] = s;
}

// ---------------------------------------------------------------------------
// P1: compose 4 comm layers -> E, F, g; then T = (1/64) F Wsum, const.
// Single CTA, f32x2 inner loops with transposed weight staging.
// ---------------------------------------------------------------------------
#define P1_WSTRIDE 68   // padded stride for transposed 64x64 weights (16B-aligned)

__global__ void p1_compose(const float* __restrict__ W1, const float* __restrict__ b1,
                           const float* __restrict__ W2, const float* __restrict__ b2,
                           const float* __restrict__ W3, const float* __restrict__ b3,
                           const float* __restrict__ W4, const float* __restrict__ b4,
                           const float* __restrict__ bdec)
{
    extern __shared__ float sm[];
    float* sE   = sm;                      // 4096
    float* sF   = sm + 4096;               // 4096
    float* sWeT = sm + 8192;               // 64*68 = 4352 (transposed: [j][k])
    float* sWbT = sm + 12544;              // 4352
    float* sG   = sm + 16896;              // 64
    // total 16960 floats

    const int t = threadIdx.x;

#pragma unroll
    for (int c = 0; c < 16; c++) {
        int idx = t + 256 * c;
        sE[idx] = ((idx >> 6) == (idx & 63)) ? 1.0f : 0.0f;
        sF[idx] = 0.0f;
    }
    if (t < 64) sG[t] = 0.0f;

    const float* Ws[4] = {W1, W2, W3, W4};
    const float* bs[4] = {b1, b2, b3, b4};

    const int ti = t >> 5;
    const int tj = t & 31;
    const int i0 = ti * 8;

#pragma unroll 1
    for (int l = 0; l < 4; l++) {
        const float* W = Ws[l];
        // stage transposed We = Wt - Wb/64 and Wb
#pragma unroll
        for (int c = 0; c < 16; c++) {
            int idx = t + 256 * c;
            int k = idx >> 6, j = idx & 63;
            float wt = W[idx];
            float wb = W[4096 + idx];
            sWeT[j * P1_WSTRIDE + k] = wt - wb * (1.0f / 64.0f);
            sWbT[j * P1_WSTRIDE + k] = wb;
        }
        __syncthreads();

        u64 aE[8][2], aF[8][2];
#pragma unroll
        for (int r = 0; r < 8; r++) {
            aE[r][0] = 0; aE[r][1] = 0; aF[r][0] = 0; aF[r][1] = 0;
        }

#pragma unroll 2
        for (int kk = 0; kk < 64; kk += 4) {
            ulonglong2 we0 = *(const ulonglong2*)&sWeT[tj * P1_WSTRIDE + kk];
            ulonglong2 we1 = *(const ulonglong2*)&sWeT[(tj + 32) * P1_WSTRIDE + kk];
            ulonglong2 wb0 = *(const ulonglong2*)&sWbT[tj * P1_WSTRIDE + kk];
            ulonglong2 wb1 = *(const ulonglong2*)&sWbT[(tj + 32) * P1_WSTRIDE + kk];
            u64 ws0x = add2(we0.x, wb0.x), ws0y = add2(we0.y, wb0.y);
            u64 ws1x = add2(we1.x, wb1.x), ws1y = add2(we1.y, wb1.y);
#pragma unroll
            for (int r = 0; r < 8; r++) {
                ulonglong2 e2 = *(const ulonglong2*)&sE[(i0 + r) * 64 + kk];
                ulonglong2 f2 = *(const ulonglong2*)&sF[(i0 + r) * 64 + kk];
                ffma2(aE[r][0], e2.x, we0.x); ffma2(aE[r][0], e2.y, we0.y);
                ffma2(aE[r][1], e2.x, we1.x); ffma2(aE[r][1], e2.y, we1.y);
                ffma2(aF[r][0], f2.x, ws0x); ffma2(aF[r][0], f2.y, ws0y);
                ffma2(aF[r][0], e2.x, wb0.x); ffma2(aF[r][0], e2.y, wb0.y);
                ffma2(aF[r][1], f2.x, ws1x); ffma2(aF[r][1], f2.y, ws1y);
                ffma2(aF[r][1], e2.x, wb1.x); ffma2(aF[r][1], e2.y, wb1.y);
            }
        }

        float gnew = 0.0f;
        if (t < 64) {
            for (int k = 0; k < 64; k++)
                gnew += sG[k] * (sWeT[t * P1_WSTRIDE + k] + sWbT[t * P1_WSTRIDE + k]);
            gnew += bs[l][t];
        }
        __syncthreads();   // all reads of old E/F/g complete

#pragma unroll
        for (int r = 0; r < 8; r++) {
            sE[(i0 + r) * 64 + tj]      = unpack_sum(aE[r][0]);
            sE[(i0 + r) * 64 + tj + 32] = unpack_sum(aE[r][1]);
            sF[(i0 + r) * 64 + tj]      = unpack_sum(aF[r][0]);
            sF[(i0 + r) * 64 + tj + 32] = unpack_sum(aF[r][1]);
        }
        if (t < 64) sG[t] = gnew;
        // next iteration's staging + __syncthreads orders these writes vs reads
    }
    __syncthreads();

    // load Wsum (precomputed by p0) into smem (reuse sWeT region: 2048 floats)
    float* sWsum = sWeT;
#pragma unroll
    for (int c = 0; c < 8; c++) {
        int idx = t + 256 * c;
        sWsum[idx] = gWsum[idx];
    }
    __syncthreads();

    // T[k][n] = (1/64) sum_d F[k][d] Wsum[d][n]
#pragma unroll
    for (int c = 0; c < 8; c++) {
        int idx = t + 256 * c;
        int k = idx >> 5, n = idx & 31;
        float s = 0.0f;
#pragma unroll 8
        for (int d = 0; d < 64; d++) s += sF[k * 64 + d] * sWsum[d * 32 + n];
        gT[idx] = s * (1.0f / 64.0f);
    }
    if (t < 32) {
        float s = 0.0f;
        for (int d = 0; d < 64; d++) s += sG[d] * sWsum[d * 32 + t];
        gConst[t] = s + bdec[t];
    }
#pragma unroll
    for (int c = 0; c < 16; c++) { int idx = t + 256 * c; gE[idx] = sE[idx]; }
}

// ---------------------------------------------------------------------------
// P2: M^T[n][a*64+k] = sum_d E[k][d] * Wdec[(a*64+d)][n] + T[k][n]
// One CTA per agent a. Mapping idx = n*64+k -> coalesced transposed stores.
// ---------------------------------------------------------------------------
__global__ void p2_buildM(const float* __restrict__ Wdec)
{
    __shared__ float sWd[2048];        // Wdec_a  [64][32]
    __shared__ float sE2[64 * 65];     // E padded [64][65]
    const int a = blockIdx.x;
    const int t = threadIdx.x;

#pragma unroll
    for (int c = 0; c < 8; c++)  sWd[t + 256 * c] = Wdec[a * 2048 + t + 256 * c];
#pragma unroll
    for (int c = 0; c < 16; c++) {
        int i = t + 256 * c;
        sE2[(i >> 6) * 65 + (i & 63)] = gE[i];
    }
    __syncthreads();

#pragma unroll
    for (int c = 0; c < 8; c++) {
        int idx = t + 256 * c;
        int n = idx >> 6, k = idx & 63;
        float acc = gT[k * 32 + n];
#pragma unroll 8
        for (int d = 0; d < 64; d++)
            acc += sE2[k * 65 + d] * sWd[d * 32 + n];
        gMT[n * 4096 + a * 64 + k] = acc;
    }
}

// ---------------------------------------------------------------------------
// Main fused kernel: encoder GEMM (f32x2, W transposed in smem) + MUFU-free
// sigmoid + decoder reduction (f32x2, M transposed in gmem).
// ---------------------------------------------------------------------------
#define WT_STRIDE 132   // transposed W_enc row stride (16B-aligned)

__global__ __launch_bounds__(TPB, 1)
void main_kernel(const float* __restrict__ O, const float* __restrict__ Wenc,
                 const float* __restrict__ benc, float* __restrict__ out)
{
    extern __shared__ float sm[];
    float* sWT  = sm;                       // 64*132 =  8448 floats (W^T [j][k])
    float* sO   = sm + 8448;                // 128*128 = 16384
    float* sH   = sm + 8448 + 16384;        // 4*4096  = 16384
    float* sB   = sH + 16384;               // 64
    float* sRed = sB + 64;                  // 1024
    // total 42304 floats = 169216 bytes

    const int t  = threadIdx.x;
    const int bb = blockIdx.x * BPC;

    // stage W_enc transposed: sWT[j][k] = Wenc[k*64+j]
#pragma unroll
    for (int c = 0; c < 32; c++) {
        int idx = t + 256 * c;              // 0..8191
        int k = idx >> 6, j = idx & 63;
        sWT[j * WT_STRIDE + k] = Wenc[idx];
    }
    if (t < 64) sB[t] = benc[t];

    const int rg = t >> 4;
    const int cg = t & 15;
    const int r0 = rg * 8;
    const int c0 = cg * 4;

#pragma unroll 1
    for (int p = 0; p < 2; p++) {
        __syncthreads();  // sWT/sB ready (p=0); sO free to reuse (p=1)

        const float4* osrc = (const float4*)(O + (size_t)(bb + 2 * p) * (64 * 128));
        float4* odst = (float4*)sO;
#pragma unroll
        for (int c = 0; c < 16; c++) odst[t + 256 * c] = osrc[t + 256 * c];
        __syncthreads();

        u64 acc2[8][4];
#pragma unroll
        for (int i = 0; i < 8; i++)
#pragma unroll
            for (int j = 0; j < 4; j++) acc2[i][j] = 0;

#pragma unroll 2
        for (int kk = 0; kk < 128; kk += 4) {
            ulonglong2 w0 = *(const ulonglong2*)&sWT[(c0 + 0) * WT_STRIDE + kk];
            ulonglong2 w1 = *(const ulonglong2*)&sWT[(c0 + 1) * WT_STRIDE + kk];
            ulonglong2 w2 = *(const ulonglong2*)&sWT[(c0 + 2) * WT_STRIDE + kk];
            ulonglong2 w3 = *(const ulonglong2*)&sWT[(c0 + 3) * WT_STRIDE + kk];
#pragma unroll
            for (int i = 0; i < 8; i++) {
                ulonglong2 o2 = *(const ulonglong2*)&sO[(r0 + i) * 128 + kk];
                ffma2(acc2[i][0], o2.x, w0.x); ffma2(acc2[i][0], o2.y, w0.y);
                ffma2(acc2[i][1], o2.x, w1.x); ffma2(acc2[i][1], o2.y, w1.y);
                ffma2(acc2[i][2], o2.x, w2.x); ffma2(acc2[i][2], o2.y, w2.y);
                ffma2(acc2[i][3], o2.x, w3.x); ffma2(acc2[i][3], o2.y, w3.y);
            }
        }

        float bx = sB[c0 + 0], by = sB[c0 + 1], bz = sB[c0 + 2], bw = sB[c0 + 3];
#pragma unroll
        for (int i = 0; i < 8; i++) {
            int row = r0 + i;
            int bl  = p * 2 + (row >> 6);
            int aa  = row & 63;
            float4 hv;
            hv.x = fast_sigmoid(unpack_sum(acc2[i][0]) + bx);
            hv.y = fast_sigmoid(unpack_sum(acc2[i][1]) + by);
            hv.z = fast_sigmoid(unpack_sum(acc2[i][2]) + bz);
            hv.w = fast_sigmoid(unpack_sum(acc2[i][3]) + bw);
            *(float4*)&sH[bl * 4096 + aa * 64 + c0] = hv;
        }
    }
    __syncthreads();

    // decoder: warp w handles rows [w*512, w*512+512), lane n -> output col n.
    // M^T row per lane streams contiguously; H is smem broadcast.
    const int w = t >> 5;
    const int n = t & 31;
    u64 dacc2[4] = {0, 0, 0, 0};
    const float* Mp = gMT + (size_t)n * 4096 + w * 512;
    const float* h0 = sH + w * 512;

#pragma unroll 4
    for (int r = 0; r < 512; r += 4) {
        ulonglong2 m2 = *(const ulonglong2*)&Mp[r];
        ulonglong2 h0v = *(const ulonglong2*)&h0[r];
        ulonglong2 h1v = *(const ulonglong2*)&h0[4096 + r];
        ulonglong2 h2v = *(const ulonglong2*)&h0[8192 + r];
        ulonglong2 h3v = *(const ulonglong2*)&h0[12288 + r];
        ffma2(dacc2[0], h0v.x, m2.x); ffma2(dacc2[0], h0v.y, m2.y);
        ffma2(dacc2[1], h1v.x, m2.x); ffma2(dacc2[1], h1v.y, m2.y);
        ffma2(dacc2[2], h2v.x, m2.x); ffma2(dacc2[2], h2v.y, m2.y);
        ffma2(dacc2[3], h3v.x, m2.x); ffma2(dacc2[3], h3v.y, m2.y);
    }

    sRed[(w * 4 + 0) * 32 + n] = unpack_sum(dacc2[0]);
    sRed[(w * 4 + 1) * 32 + n] = unpack_sum(dacc2[1]);
    sRed[(w * 4 + 2) * 32 + n] = unpack_sum(dacc2[2]);
    sRed[(w * 4 + 3) * 32 + n] = unpack_sum(dacc2[3]);
    __syncthreads();

    if (t < 128) {
        int b  = t >> 5;
        int nn = t & 31;
        float s = gConst[nn];
#pragma unroll
        for (int ww = 0; ww < 8; ww++) s += sRed[(ww * 4 + b) * 32 + nn];
        out[(size_t)(bb + b) * 32 + nn] = s;
    }
}

// ---------------------------------------------------------------------------
extern "C" void kernel_launch(void* const* d_in, const int* in_sizes, int n_in,
                              void* d_out, int out_size)
{
    const float* O    = (const float*)d_in[0];
    const float* Wenc = (const float*)d_in[1];
    const float* benc = (const float*)d_in[2];
    const float* W1   = (const float*)d_in[3];
    const float* b1   = (const float*)d_in[4];
    const float* W2   = (const float*)d_in[5];
    const float* b2   = (const float*)d_in[6];
    const float* W3   = (const float*)d_in[7];
    const float* b3   = (const float*)d_in[8];
    const float* W4   = (const float*)d_in[9];
    const float* b4   = (const float*)d_in[10];
    const float* Wdec = (const float*)d_in[11];
    const float* bdec = (const float*)d_in[12];
    float* out = (float*)d_out;

    cudaFuncSetAttribute(p1_compose,  cudaFuncAttributeMaxDynamicSharedMemorySize, 16960 * 4);
    cudaFuncSetAttribute(main_kernel, cudaFuncAttributeMaxDynamicSharedMemorySize, 42304 * 4);

    p0_wsum<<<8, 256>>>(Wdec);
    p1_compose<<<1, 256, 16960 * 4>>>(W1, b1, W2, b2, W3, b3, W4, b4, bdec);
    p2_buildM<<<64, 256>>>(Wdec);
    main_kernel<<<NBATCH / BPC, TPB, 42304 * 4>>>(O, Wenc, benc, out);
}

// round 11
// speedup vs baseline: 1.0003x; 1.0003x over previous
#include <cuda_runtime.h>
#include <cstddef>

// ============================================================================
// CommNetActor — algebraically collapsed + f32x2 packed FMA + MUFU-free sigmoid.
//
//   H0 = sigmoid(O @ W_enc + b_enc)                      [B, A, 64]
//   4 comm layers (all LINEAR) + decoder compose into:
//   out[b] = H0[b].flatten() @ M + const                 M: [4096, 32]
//
// Comm layer: H' = H (Wt - Wb/64) + (1/64) J H Wb + 1 b^T    (J = ones(64,64))
// Closure:    E' = E We ; F' = F(We+Wb) + E Wb ; g' = (We+Wb)^T g + b
// Decoder:    M[(a,k),n] = (E Wdec_a)[k][n] + (1/64 F Wsum)[k][n]
//             const = Wsum^T g + b_dec,  Wsum = sum_a Wdec_a
//
// Perf model: prior kernel was MUFU-bound (67M MUFU = ~500us). This version:
//  - sigmoid with zero MUFU (poly exp2 + Newton rcp)
//  - fma.rn.f32x2 (FFMA2) pairing the K dimension -> 2x FMA throughput,
//    no pack ops (W stored transposed; M stored transposed)
// ============================================================================

#define TPB 256
#define BPC 4
#define NBATCH 8192

typedef unsigned long long u64;

__device__ float gE[64 * 64];
__device__ float gT[64 * 32];
__device__ float gConst[32];
__device__ float gWsum[64 * 32];
__device__ float gMT[32 * 4096];     // M transposed: [n][a*64+k]

// ---------------------------------------------------------------------------
__device__ __forceinline__ void ffma2(u64& d, u64 a, u64 b) {
    asm("fma.rn.f32x2 %0, %1, %2, %0;" : "+l"(d) : "l"(a), "l"(b));
}
__device__ __forceinline__ u64 add2(u64 a, u64 b) {
    u64 d; asm("add.rn.f32x2 %0, %1, %2;" : "=l"(d) : "l"(a), "l"(b)); return d;
}
__device__ __forceinline__ float unpack_sum(u64 v) {
    float lo, hi;
    asm("mov.b64 {%0, %1}, %2;" : "=f"(lo), "=f"(hi) : "l"(v));
    return lo + hi;
}

// MUFU-free sigmoid: 1/(1+2^(-x*log2e)). ~18 FMA/ALU ops, rel err ~3e-6.
__device__ __forceinline__ float fast_sigmoid(float x) {
    float t = x * -1.44269504088896f;
    t = fminf(fmaxf(t, -126.0f), 126.0f);
    float fi = t + 12582912.0f;                       // 1.5*2^23 magic round
    int   ib = __float_as_int(fi) - 0x4B400000;       // = rint(t)
    float f  = t - (fi - 12582912.0f);                // f in [-0.5, 0.5]
    float p  = 1.3333558e-3f;                         // 2^f Taylor/minimax deg-5
    p = fmaf(p, f, 9.6181291e-3f);
    p = fmaf(p, f, 5.5504109e-2f);
    p = fmaf(p, f, 2.4022651e-1f);
    p = fmaf(p, f, 6.9314718e-1f);
    p = fmaf(p, f, 1.0f);
    float e = __int_as_float(__float_as_int(p) + (int)((unsigned)ib << 23));
    float d = 1.0f + e;
    float r = __int_as_float(0x7EF311C3 - __float_as_int(d));   // rcp seed
    r = r * (2.0f - d * r);
    r = r * (2.0f - d * r);
    return r;
}

// ---------------------------------------------------------------------------
// P0: Wsum[d][n] = sum_a Wdec[(a*64+d)][n]. Parallel (was DRAM-latency bound
// inside single-CTA p1).
// ---------------------------------------------------------------------------
__global__ void p0_wsum(const float* __restrict__ Wdec)
{
    int idx = blockIdx.x * 256 + threadIdx.x;   // 0..2047
    float s = 0.0f;
#pragma unroll 8
    for (int a = 0; a < 64; a++) s += Wdec[a * 2048 + idx];
    gWsum[idx] = s;
}

// ---------------------------------------------------------------------------
// P1: compose 4 comm layers -> E, F, g; then T = (1/64) F Wsum, const.
// Single CTA, f32x2 inner loops with transposed weight staging.
// ---------------------------------------------------------------------------
#define P1_WSTRIDE 68   // padded stride for transposed 64x64 weights (16B-aligned)

__global__ void p1_compose(const float* __restrict__ W1, const float* __restrict__ b1,
                           const float* __restrict__ W2, const float* __restrict__ b2,
                           const float* __restrict__ W3, const float* __restrict__ b3,
                           const float* __restrict__ W4, const float* __restrict__ b4,
                           const float* __restrict__ bdec)
{
    extern __shared__ float sm[];
    float* sE   = sm;                      // 4096
    float* sF   = sm + 4096;               // 4096
    float* sWeT = sm + 8192;               // 64*68 = 4352 (transposed: [j][k])
    float* sWbT = sm + 12544;              // 4352
    float* sG   = sm + 16896;              // 64
    // total 16960 floats

    const int t = threadIdx.x;

#pragma unroll
    for (int c = 0; c < 16; c++) {
        int idx = t + 256 * c;
        sE[idx] = ((idx >> 6) == (idx & 63)) ? 1.0f : 0.0f;
        sF[idx] = 0.0f;
    }
    if (t < 64) sG[t] = 0.0f;

    const float* Ws[4] = {W1, W2, W3, W4};
    const float* bs[4] = {b1, b2, b3, b4};

    const int ti = t >> 5;
    const int tj = t & 31;
    const int i0 = ti * 8;

#pragma unroll 1
    for (int l = 0; l < 4; l++) {
        const float* W = Ws[l];
        // stage transposed We = Wt - Wb/64 and Wb
#pragma unroll
        for (int c = 0; c < 16; c++) {
            int idx = t + 256 * c;
            int k = idx >> 6, j = idx & 63;
            float wt = W[idx];
            float wb = W[4096 + idx];
            sWeT[j * P1_WSTRIDE + k] = wt - wb * (1.0f / 64.0f);
            sWbT[j * P1_WSTRIDE + k] = wb;
        }
        __syncthreads();

        u64 aE[8][2], aF[8][2];
#pragma unroll
        for (int r = 0; r < 8; r++) {
            aE[r][0] = 0; aE[r][1] = 0; aF[r][0] = 0; aF[r][1] = 0;
        }

#pragma unroll 2
        for (int kk = 0; kk < 64; kk += 4) {
            ulonglong2 we0 = *(const ulonglong2*)&sWeT[tj * P1_WSTRIDE + kk];
            ulonglong2 we1 = *(const ulonglong2*)&sWeT[(tj + 32) * P1_WSTRIDE + kk];
            ulonglong2 wb0 = *(const ulonglong2*)&sWbT[tj * P1_WSTRIDE + kk];
            ulonglong2 wb1 = *(const ulonglong2*)&sWbT[(tj + 32) * P1_WSTRIDE + kk];
            u64 ws0x = add2(we0.x, wb0.x), ws0y = add2(we0.y, wb0.y);
            u64 ws1x = add2(we1.x, wb1.x), ws1y = add2(we1.y, wb1.y);
#pragma unroll
            for (int r = 0; r < 8; r++) {
                ulonglong2 e2 = *(const ulonglong2*)&sE[(i0 + r) * 64 + kk];
                ulonglong2 f2 = *(const ulonglong2*)&sF[(i0 + r) * 64 + kk];
                ffma2(aE[r][0], e2.x, we0.x); ffma2(aE[r][0], e2.y, we0.y);
                ffma2(aE[r][1], e2.x, we1.x); ffma2(aE[r][1], e2.y, we1.y);
                ffma2(aF[r][0], f2.x, ws0x); ffma2(aF[r][0], f2.y, ws0y);
                ffma2(aF[r][0], e2.x, wb0.x); ffma2(aF[r][0], e2.y, wb0.y);
                ffma2(aF[r][1], f2.x, ws1x); ffma2(aF[r][1], f2.y, ws1y);
                ffma2(aF[r][1], e2.x, wb1.x); ffma2(aF[r][1], e2.y, wb1.y);
            }
        }

        float gnew = 0.0f;
        if (t < 64) {
            for (int k = 0; k < 64; k++)
                gnew += sG[k] * (sWeT[t * P1_WSTRIDE + k] + sWbT[t * P1_WSTRIDE + k]);
            gnew += bs[l][t];
        }
        __syncthreads();   // all reads of old E/F/g complete

#pragma unroll
        for (int r = 0; r < 8; r++) {
            sE[(i0 + r) * 64 + tj]      = unpack_sum(aE[r][0]);
            sE[(i0 + r) * 64 + tj + 32] = unpack_sum(aE[r][1]);
            sF[(i0 + r) * 64 + tj]      = unpack_sum(aF[r][0]);
            sF[(i0 + r) * 64 + tj + 32] = unpack_sum(aF[r][1]);
        }
        if (t < 64) sG[t] = gnew;
        // next iteration's staging + __syncthreads orders these writes vs reads
    }
    __syncthreads();

    // load Wsum (precomputed by p0) into smem (reuse sWeT region: 2048 floats)
    float* sWsum = sWeT;
#pragma unroll
    for (int c = 0; c < 8; c++) {
        int idx = t + 256 * c;
        sWsum[idx] = gWsum[idx];
    }
    __syncthreads();

    // T[k][n] = (1/64) sum_d F[k][d] Wsum[d][n]
#pragma unroll
    for (int c = 0; c < 8; c++) {
        int idx = t + 256 * c;
        int k = idx >> 5, n = idx & 31;
        float s = 0.0f;
#pragma unroll 8
        for (int d = 0; d < 64; d++) s += sF[k * 64 + d] * sWsum[d * 32 + n];
        gT[idx] = s * (1.0f / 64.0f);
    }
    if (t < 32) {
        float s = 0.0f;
        for (int d = 0; d < 64; d++) s += sG[d] * sWsum[d * 32 + t];
        gConst[t] = s + bdec[t];
    }
#pragma unroll
    for (int c = 0; c < 16; c++) { int idx = t + 256 * c; gE[idx] = sE[idx]; }
}

// ---------------------------------------------------------------------------
// P2: M^T[n][a*64+k] = sum_d E[k][d] * Wdec[(a*64+d)][n] + T[k][n]
// One CTA per agent a. Mapping idx = n*64+k -> coalesced transposed stores.
// ---------------------------------------------------------------------------
__global__ void p2_buildM(const float* __restrict__ Wdec)
{
    __shared__ float sWd[2048];        // Wdec_a  [64][32]
    __shared__ float sE2[64 * 65];     // E padded [64][65]
    const int a = blockIdx.x;
    const int t = threadIdx.x;

#pragma unroll
    for (int c = 0; c < 8; c++)  sWd[t + 256 * c] = Wdec[a * 2048 + t + 256 * c];
#pragma unroll
    for (int c = 0; c < 16; c++) {
        int i = t + 256 * c;
        sE2[(i >> 6) * 65 + (i & 63)] = gE[i];
    }
    __syncthreads();

#pragma unroll
    for (int c = 0; c < 8; c++) {
        int idx = t + 256 * c;
        int n = idx >> 6, k = idx & 63;
        float acc = gT[k * 32 + n];
#pragma unroll 8
        for (int d = 0; d < 64; d++)
            acc += sE2[k * 65 + d] * sWd[d * 32 + n];
        gMT[n * 4096 + a * 64 + k] = acc;
    }
}

// ---------------------------------------------------------------------------
// Main fused kernel: encoder GEMM (f32x2, W transposed in smem) + MUFU-free
// sigmoid + decoder reduction (f32x2, M transposed in gmem).
// ---------------------------------------------------------------------------
#define WT_STRIDE 132   // transposed W_enc row stride (16B-aligned)

__global__ __launch_bounds__(TPB, 1)
void main_kernel(const float* __restrict__ O, const float* __restrict__ Wenc,
                 const float* __restrict__ benc, float* __restrict__ out)
{
    extern __shared__ float sm[];
    float* sWT  = sm;                       // 64*132 =  8448 floats (W^T [j][k])
    float* sO   = sm + 8448;                // 128*128 = 16384
    float* sH   = sm + 8448 + 16384;        // 4*4096  = 16384
    float* sB   = sH + 16384;               // 64
    float* sRed = sB + 64;                  // 1024
    // total 42304 floats = 169216 bytes

    const int t  = threadIdx.x;
    const int bb = blockIdx.x * BPC;

    // stage W_enc transposed: sWT[j][k] = Wenc[k*64+j]
#pragma unroll
    for (int c = 0; c < 32; c++) {
        int idx = t + 256 * c;              // 0..8191
        int k = idx >> 6, j = idx & 63;
        sWT[j * WT_STRIDE + k] = Wenc[idx];
    }
    if (t < 64) sB[t] = benc[t];

    const int rg = t >> 4;
    const int cg = t & 15;
    const int r0 = rg * 8;
    const int c0 = cg * 4;

#pragma unroll 1
    for (int p = 0; p < 2; p++) {
        __syncthreads();  // sWT/sB ready (p=0); sO free to reuse (p=1)

        const float4* osrc = (const float4*)(O + (size_t)(bb + 2 * p) * (64 * 128));
        float4* odst = (float4*)sO;
#pragma unroll
        for (int c = 0; c < 16; c++) odst[t + 256 * c] = osrc[t + 256 * c];
        __syncthreads();

        u64 acc2[8][4];
#pragma unroll
        for (int i = 0; i < 8; i++)
#pragma unroll
            for (int j = 0; j < 4; j++) acc2[i][j] = 0;

#pragma unroll 2
        for (int kk = 0; kk < 128; kk += 4) {
            ulonglong2 w0 = *(const ulonglong2*)&sWT[(c0 + 0) * WT_STRIDE + kk];
            ulonglong2 w1 = *(const ulonglong2*)&sWT[(c0 + 1) * WT_STRIDE + kk];
            ulonglong2 w2 = *(const ulonglong2*)&sWT[(c0 + 2) * WT_STRIDE + kk];
            ulonglong2 w3 = *(const ulonglong2*)&sWT[(c0 + 3) * WT_STRIDE + kk];
#pragma unroll
            for (int i = 0; i < 8; i++) {
                ulonglong2 o2 = *(const ulonglong2*)&sO[(r0 + i) * 128 + kk];
                ffma2(acc2[i][0], o2.x, w0.x); ffma2(acc2[i][0], o2.y, w0.y);
                ffma2(acc2[i][1], o2.x, w1.x); ffma2(acc2[i][1], o2.y, w1.y);
                ffma2(acc2[i][2], o2.x, w2.x); ffma2(acc2[i][2], o2.y, w2.y);
                ffma2(acc2[i][3], o2.x, w3.x); ffma2(acc2[i][3], o2.y, w3.y);
            }
        }

        float bx = sB[c0 + 0], by = sB[c0 + 1], bz = sB[c0 + 2], bw = sB[c0 + 3];
#pragma unroll
        for (int i = 0; i < 8; i++) {
            int row = r0 + i;
            int bl  = p * 2 + (row >> 6);
            int aa  = row & 63;
            float4 hv;
            hv.x = fast_sigmoid(unpack_sum(acc2[i][0]) + bx);
            hv.y = fast_sigmoid(unpack_sum(acc2[i][1]) + by);
            hv.z = fast_sigmoid(unpack_sum(acc2[i][2]) + bz);
            hv.w = fast_sigmoid(unpack_sum(acc2[i][3]) + bw);
            *(float4*)&sH[bl * 4096 + aa * 64 + c0] = hv;
        }
    }
    __syncthreads();

    // decoder: warp w handles rows [w*512, w*512+512), lane n -> output col n.
    // M^T row per lane streams contiguously; H is smem broadcast.
    const int w = t >> 5;
    const int n = t & 31;
    u64 dacc2[4] = {0, 0, 0, 0};
    const float* Mp = gMT + (size_t)n * 4096 + w * 512;
    const float* h0 = sH + w * 512;

#pragma unroll 4
    for (int r = 0; r < 512; r += 4) {
        ulonglong2 m2 = *(const ulonglong2*)&Mp[r];
        ulonglong2 h0v = *(const ulonglong2*)&h0[r];
        ulonglong2 h1v = *(const ulonglong2*)&h0[4096 + r];
        ulonglong2 h2v = *(const ulonglong2*)&h0[8192 + r];
        ulonglong2 h3v = *(const ulonglong2*)&h0[12288 + r];
        ffma2(dacc2[0], h0v.x, m2.x); ffma2(dacc2[0], h0v.y, m2.y);
        ffma2(dacc2[1], h1v.x, m2.x); ffma2(dacc2[1], h1v.y, m2.y);
        ffma2(dacc2[2], h2v.x, m2.x); ffma2(dacc2[2], h2v.y, m2.y);
        ffma2(dacc2[3], h3v.x, m2.x); ffma2(dacc2[3], h3v.y, m2.y);
    }

    sRed[(w * 4 + 0) * 32 + n] = unpack_sum(dacc2[0]);
    sRed[(w * 4 + 1) * 32 + n] = unpack_sum(dacc2[1]);
    sRed[(w * 4 + 2) * 32 + n] = unpack_sum(dacc2[2]);
    sRed[(w * 4 + 3) * 32 + n] = unpack_sum(dacc2[3]);
    __syncthreads();

    if (t < 128) {
        int b  = t >> 5;
        int nn = t & 31;
        float s = gConst[nn];
#pragma unroll
        for (int ww = 0; ww < 8; ww++) s += sRed[(ww * 4 + b) * 32 + nn];
        out[(size_t)(bb + b) * 32 + nn] = s;
    }
}

// ---------------------------------------------------------------------------
extern "C" void kernel_launch(void* const* d_in, const int* in_sizes, int n_in,
                              void* d_out, int out_size)
{
    const float* O    = (const float*)d_in[0];
    const float* Wenc = (const float*)d_in[1];
    const float* benc = (const float*)d_in[2];
    const float* W1   = (const float*)d_in[3];
    const float* b1   = (const float*)d_in[4];
    const float* W2   = (const float*)d_in[5];
    const float* b2   = (const float*)d_in[6];
    const float* W3   = (const float*)d_in[7];
    const float* b3   = (const float*)d_in[8];
    const float* W4   = (const float*)d_in[9];
    const float* b4   = (const float*)d_in[10];
    const float* Wdec = (const float*)d_in[11];
    const float* bdec = (const float*)d_in[12];
    float* out = (float*)d_out;

    cudaFuncSetAttribute(p1_compose,  cudaFuncAttributeMaxDynamicSharedMemorySize, 16960 * 4);
    cudaFuncSetAttribute(main_kernel, cudaFuncAttributeMaxDynamicSharedMemorySize, 42304 * 4);

    p0_wsum<<<8, 256>>>(Wdec);
    p1_compose<<<1, 256, 16960 * 4>>>(W1, b1, W2, b2, W3, b3, W4, b4, bdec);
    p2_buildM<<<64, 256>>>(Wdec);
    main_kernel<<<NBATCH / BPC, TPB, 42304 * 4>>>(O, Wenc, benc, out);
}

// round 13
// speedup vs baseline: 1.2396x; 1.2392x over previous
#include <cuda_runtime.h>
#include <cstddef>

// ============================================================================
// CommNetActor — algebraically collapsed + f32x2 packed FMA + MUFU-free sigmoid.
//
//   H0 = sigmoid(O @ W_enc + b_enc)                      [B, A, 64]
//   4 comm layers (all LINEAR) + decoder compose into:
//   out[b] = H0[b].flatten() @ M + const                 M: [4096, 32]
//
// R11 post-mortem: L1=85.9%/fma=22.6% -> smem-bound. Cause: W^T loads had
// inter-lane stride 2112B = 64 mod 128 -> 4-way bank conflict per LDS.128
// phase. Fix: thread covers columns {cg, cg+16, cg+32, cg+48} so lane stride
// is 528B = 16 mod 128 -> conflict-free (8 distinct 16B chunks per quarter
// warp). Also: p1 widened to 512 threads (serial prologue was 77us).
// ============================================================================

#define TPB 256
#define BPC 4
#define NBATCH 8192

typedef unsigned long long u64;

__device__ float gE[64 * 64];
__device__ float gT[64 * 32];
__device__ float gConst[32];
__device__ float gWsum[64 * 32];
__device__ float gMT[32 * 4096];     // M transposed: [n][a*64+k]

// ---------------------------------------------------------------------------
__device__ __forceinline__ void ffma2(u64& d, u64 a, u64 b) {
    asm("fma.rn.f32x2 %0, %1, %2, %0;" : "+l"(d) : "l"(a), "l"(b));
}
__device__ __forceinline__ u64 add2(u64 a, u64 b) {
    u64 d; asm("add.rn.f32x2 %0, %1, %2;" : "=l"(d) : "l"(a), "l"(b)); return d;
}
__device__ __forceinline__ float unpack_sum(u64 v) {
    float lo, hi;
    asm("mov.b64 {%0, %1}, %2;" : "=f"(lo), "=f"(hi) : "l"(v));
    return lo + hi;
}

// MUFU-free sigmoid: 1/(1+2^(-x*log2e)). ~18 FMA/ALU ops, rel err ~3e-6.
__device__ __forceinline__ float fast_sigmoid(float x) {
    float t = x * -1.44269504088896f;
    t = fminf(fmaxf(t, -126.0f), 126.0f);
    float fi = t + 12582912.0f;                       // 1.5*2^23 magic round
    int   ib = __float_as_int(fi) - 0x4B400000;       // = rint(t)
    float f  = t - (fi - 12582912.0f);                // f in [-0.5, 0.5]
    float p  = 1.3333558e-3f;                         // 2^f minimax deg-5
    p = fmaf(p, f, 9.6181291e-3f);
    p = fmaf(p, f, 5.5504109e-2f);
    p = fmaf(p, f, 2.4022651e-1f);
    p = fmaf(p, f, 6.9314718e-1f);
    p = fmaf(p, f, 1.0f);
    float e = __int_as_float(__float_as_int(p) + (int)((unsigned)ib << 23));
    float d = 1.0f + e;
    float r = __int_as_float(0x7EF311C3 - __float_as_int(d));   // rcp seed
    r = r * (2.0f - d * r);
    r = r * (2.0f - d * r);
    return r;
}

// ---------------------------------------------------------------------------
// P0: Wsum[d][n] = sum_a Wdec[(a*64+d)][n].
// ---------------------------------------------------------------------------
__global__ void p0_wsum(const float* __restrict__ Wdec)
{
    int idx = blockIdx.x * 256 + threadIdx.x;   // 0..2047
    float s = 0.0f;
#pragma unroll 8
    for (int a = 0; a < 64; a++) s += Wdec[a * 2048 + idx];
    gWsum[idx] = s;
}

// ---------------------------------------------------------------------------
// P1: compose 4 comm layers -> E, F, g; then T = (1/64) F Wsum, const.
// Single CTA, 512 threads (was 256: serial latency-bound), f32x2 inner loops.
// ---------------------------------------------------------------------------
#define P1_TPB 512
#define P1_WSTRIDE 68   // 68 mod 32 == 4 -> 16B lane stride, conflict-free

__global__ void p1_compose(const float* __restrict__ W1, const float* __restrict__ b1,
                           const float* __restrict__ W2, const float* __restrict__ b2,
                           const float* __restrict__ W3, const float* __restrict__ b3,
                           const float* __restrict__ W4, const float* __restrict__ b4,
                           const float* __restrict__ bdec)
{
    extern __shared__ float sm[];
    float* sE   = sm;                      // 4096
    float* sF   = sm + 4096;               // 4096
    float* sWeT = sm + 8192;               // 64*68 = 4352 (transposed: [j][k])
    float* sWbT = sm + 12544;              // 4352
    float* sG   = sm + 16896;              // 64
    // total 16960 floats

    const int t = threadIdx.x;

#pragma unroll
    for (int c = 0; c < 8; c++) {
        int idx = t + P1_TPB * c;
        sE[idx] = ((idx >> 6) == (idx & 63)) ? 1.0f : 0.0f;
        sF[idx] = 0.0f;
    }
    if (t < 64) sG[t] = 0.0f;

    const float* Ws[4] = {W1, W2, W3, W4};
    const float* bs[4] = {b1, b2, b3, b4};

    const int ti = t >> 5;        // 0..15 -> 4 rows each
    const int tj = t & 31;
    const int i0 = ti * 4;

#pragma unroll 1
    for (int l = 0; l < 4; l++) {
        const float* W = Ws[l];
#pragma unroll
        for (int c = 0; c < 8; c++) {
            int idx = t + P1_TPB * c;
            int k = idx >> 6, j = idx & 63;
            float wt = W[idx];
            float wb = W[4096 + idx];
            sWeT[j * P1_WSTRIDE + k] = wt - wb * (1.0f / 64.0f);
            sWbT[j * P1_WSTRIDE + k] = wb;
        }
        __syncthreads();

        u64 aE[4][2], aF[4][2];
#pragma unroll
        for (int r = 0; r < 4; r++) {
            aE[r][0] = 0; aE[r][1] = 0; aF[r][0] = 0; aF[r][1] = 0;
        }

#pragma unroll 2
        for (int kk = 0; kk < 64; kk += 4) {
            ulonglong2 we0 = *(const ulonglong2*)&sWeT[tj * P1_WSTRIDE + kk];
            ulonglong2 we1 = *(const ulonglong2*)&sWeT[(tj + 32) * P1_WSTRIDE + kk];
            ulonglong2 wb0 = *(const ulonglong2*)&sWbT[tj * P1_WSTRIDE + kk];
            ulonglong2 wb1 = *(const ulonglong2*)&sWbT[(tj + 32) * P1_WSTRIDE + kk];
            u64 ws0x = add2(we0.x, wb0.x), ws0y = add2(we0.y, wb0.y);
            u64 ws1x = add2(we1.x, wb1.x), ws1y = add2(we1.y, wb1.y);
#pragma unroll
            for (int r = 0; r < 4; r++) {
                ulonglong2 e2 = *(const ulonglong2*)&sE[(i0 + r) * 64 + kk];
                ulonglong2 f2 = *(const ulonglong2*)&sF[(i0 + r) * 64 + kk];
                ffma2(aE[r][0], e2.x, we0.x); ffma2(aE[r][0], e2.y, we0.y);
                ffma2(aE[r][1], e2.x, we1.x); ffma2(aE[r][1], e2.y, we1.y);
                ffma2(aF[r][0], f2.x, ws0x); ffma2(aF[r][0], f2.y, ws0y);
                ffma2(aF[r][0], e2.x, wb0.x); ffma2(aF[r][0], e2.y, wb0.y);
                ffma2(aF[r][1], f2.x, ws1x); ffma2(aF[r][1], f2.y, ws1y);
                ffma2(aF[r][1], e2.x, wb1.x); ffma2(aF[r][1], e2.y, wb1.y);
            }
        }

        float gnew = 0.0f;
        if (t < 64) {
            for (int k = 0; k < 64; k++)
                gnew += sG[k] * (sWeT[t * P1_WSTRIDE + k] + sWbT[t * P1_WSTRIDE + k]);
            gnew += bs[l][t];
        }
        __syncthreads();   // all reads of old E/F/g complete

#pragma unroll
        for (int r = 0; r < 4; r++) {
            sE[(i0 + r) * 64 + tj]      = unpack_sum(aE[r][0]);
            sE[(i0 + r) * 64 + tj + 32] = unpack_sum(aE[r][1]);
            sF[(i0 + r) * 64 + tj]      = unpack_sum(aF[r][0]);
            sF[(i0 + r) * 64 + tj + 32] = unpack_sum(aF[r][1]);
        }
        if (t < 64) sG[t] = gnew;
        // next iteration's staging sync orders these writes vs reads
    }
    __syncthreads();

    float* sWsum = sWeT;   // reuse (2048 floats)
#pragma unroll
    for (int c = 0; c < 4; c++) {
        int idx = t + P1_TPB * c;
        sWsum[idx] = gWsum[idx];
    }
    __syncthreads();

    // T[k][n] = (1/64) sum_d F[k][d] Wsum[d][n]
#pragma unroll
    for (int c = 0; c < 4; c++) {
        int idx = t + P1_TPB * c;
        int k = idx >> 5, n = idx & 31;
        float s = 0.0f;
#pragma unroll 8
        for (int d = 0; d < 64; d++) s += sF[k * 64 + d] * sWsum[d * 32 + n];
        gT[idx] = s * (1.0f / 64.0f);
    }
    if (t < 32) {
        float s = 0.0f;
        for (int d = 0; d < 64; d++) s += sG[d] * sWsum[d * 32 + t];
        gConst[t] = s + bdec[t];
    }
#pragma unroll
    for (int c = 0; c < 8; c++) { int idx = t + P1_TPB * c; gE[idx] = sE[idx]; }
}

// ---------------------------------------------------------------------------
// P2: M^T[n][a*64+k] = sum_d E[k][d] * Wdec[(a*64+d)][n] + T[k][n]
// ---------------------------------------------------------------------------
__global__ void p2_buildM(const float* __restrict__ Wdec)
{
    __shared__ float sWd[2048];        // Wdec_a  [64][32]
    __shared__ float sE2[64 * 65];     // E padded [64][65]
    const int a = blockIdx.x;
    const int t = threadIdx.x;

#pragma unroll
    for (int c = 0; c < 8; c++)  sWd[t + 256 * c] = Wdec[a * 2048 + t + 256 * c];
#pragma unroll
    for (int c = 0; c < 16; c++) {
        int i = t + 256 * c;
        sE2[(i >> 6) * 65 + (i & 63)] = gE[i];
    }
    __syncthreads();

#pragma unroll
    for (int c = 0; c < 8; c++) {
        int idx = t + 256 * c;
        int n = idx >> 6, k = idx & 63;
        float acc = gT[k * 32 + n];
#pragma unroll 8
        for (int d = 0; d < 64; d++)
            acc += sE2[k * 65 + d] * sWd[d * 32 + n];
        gMT[n * 4096 + a * 64 + k] = acc;
    }
}

// ---------------------------------------------------------------------------
// Main fused kernel. Thread tile: 8 rows x 4 cols, cols = {cg, cg+16, cg+32,
// cg+48} (cg = t&15) -> W^T lane stride 528B = 16 mod 128: conflict-free.
// ---------------------------------------------------------------------------
#define WT_STRIDE 132   // 132 mod 32 == 4 -> 16B lane stride at col step 1

__global__ __launch_bounds__(TPB, 1)
void main_kernel(const float* __restrict__ O, const float* __restrict__ Wenc,
                 const float* __restrict__ benc, float* __restrict__ out)
{
    extern __shared__ float sm[];
    float* sWT  = sm;                       // 64*132 =  8448 floats (W^T [j][k])
    float* sO   = sm + 8448;                // 128*128 = 16384
    float* sH   = sm + 8448 + 16384;        // 4*4096  = 16384
    float* sB   = sH + 16384;               // 64
    float* sRed = sB + 64;                  // 1024
    // total 42304 floats = 169216 bytes

    const int t  = threadIdx.x;
    const int bb = blockIdx.x * BPC;

    // stage W_enc transposed: sWT[j][k] = Wenc[k*64+j]
#pragma unroll
    for (int c = 0; c < 32; c++) {
        int idx = t + 256 * c;              // 0..8191
        int k = idx >> 6, j = idx & 63;
        sWT[j * WT_STRIDE + k] = Wenc[idx];
    }
    if (t < 64) sB[t] = benc[t];

    const int rg = t >> 4;      // 16 row groups of 8 rows
    const int cg = t & 15;      // cols cg, cg+16, cg+32, cg+48
    const int r0 = rg * 8;

#pragma unroll 1
    for (int p = 0; p < 2; p++) {
        __syncthreads();  // sWT/sB ready (p=0); sO free to reuse (p=1)

        const float4* osrc = (const float4*)(O + (size_t)(bb + 2 * p) * (64 * 128));
        float4* odst = (float4*)sO;
#pragma unroll
        for (int c = 0; c < 16; c++) odst[t + 256 * c] = osrc[t + 256 * c];
        __syncthreads();

        u64 acc2[8][4];
#pragma unroll
        for (int i = 0; i < 8; i++)
#pragma unroll
            for (int j = 0; j < 4; j++) acc2[i][j] = 0;

#pragma unroll 2
        for (int kk = 0; kk < 128; kk += 4) {
            ulonglong2 w0 = *(const ulonglong2*)&sWT[(cg +  0) * WT_STRIDE + kk];
            ulonglong2 w1 = *(const ulonglong2*)&sWT[(cg + 16) * WT_STRIDE + kk];
            ulonglong2 w2 = *(const ulonglong2*)&sWT[(cg + 32) * WT_STRIDE + kk];
            ulonglong2 w3 = *(const ulonglong2*)&sWT[(cg + 48) * WT_STRIDE + kk];
#pragma unroll
            for (int i = 0; i < 8; i++) {
                ulonglong2 o2 = *(const ulonglong2*)&sO[(r0 + i) * 128 + kk];
                ffma2(acc2[i][0], o2.x, w0.x); ffma2(acc2[i][0], o2.y, w0.y);
                ffma2(acc2[i][1], o2.x, w1.x); ffma2(acc2[i][1], o2.y, w1.y);
                ffma2(acc2[i][2], o2.x, w2.x); ffma2(acc2[i][2], o2.y, w2.y);
                ffma2(acc2[i][3], o2.x, w3.x); ffma2(acc2[i][3], o2.y, w3.y);
            }
        }

        float b0 = sB[cg], b1 = sB[cg + 16], b2 = sB[cg + 32], b3 = sB[cg + 48];
#pragma unroll
        for (int i = 0; i < 8; i++) {
            int row = r0 + i;
            int bl  = p * 2 + (row >> 6);
            int aa  = row & 63;
            float* dst = &sH[bl * 4096 + aa * 64 + cg];
            dst[0]  = fast_sigmoid(unpack_sum(acc2[i][0]) + b0);
            dst[16] = fast_sigmoid(unpack_sum(acc2[i][1]) + b1);
            dst[32] = fast_sigmoid(unpack_sum(acc2[i][2]) + b2);
            dst[48] = fast_sigmoid(unpack_sum(acc2[i][3]) + b3);
        }
    }
    __syncthreads();

    // decoder: warp w handles rows [w*512, w*512+512), lane n -> output col n.
    const int w = t >> 5;
    const int n = t & 31;
    u64 dacc2[4] = {0, 0, 0, 0};
    const float* Mp = gMT + (size_t)n * 4096 + w * 512;
    const float* h0 = sH + w * 512;

#pragma unroll 4
    for (int r = 0; r < 512; r += 4) {
        ulonglong2 m2 = *(const ulonglong2*)&Mp[r];
        ulonglong2 h0v = *(const ulonglong2*)&h0[r];
        ulonglong2 h1v = *(const ulonglong2*)&h0[4096 + r];
        ulonglong2 h2v = *(const ulonglong2*)&h0[8192 + r];
        ulonglong2 h3v = *(const ulonglong2*)&h0[12288 + r];
        ffma2(dacc2[0], h0v.x, m2.x); ffma2(dacc2[0], h0v.y, m2.y);
        ffma2(dacc2[1], h1v.x, m2.x); ffma2(dacc2[1], h1v.y, m2.y);
        ffma2(dacc2[2], h2v.x, m2.x); ffma2(dacc2[2], h2v.y, m2.y);
        ffma2(dacc2[3], h3v.x, m2.x); ffma2(dacc2[3], h3v.y, m2.y);
    }

    sRed[(w * 4 + 0) * 32 + n] = unpack_sum(dacc2[0]);
    sRed[(w * 4 + 1) * 32 + n] = unpack_sum(dacc2[1]);
    sRed[(w * 4 + 2) * 32 + n] = unpack_sum(dacc2[2]);
    sRed[(w * 4 + 3) * 32 + n] = unpack_sum(dacc2[3]);
    __syncthreads();

    if (t < 128) {
        int b  = t >> 5;
        int nn = t & 31;
        float s = gConst[nn];
#pragma unroll
        for (int ww = 0; ww < 8; ww++) s += sRed[(ww * 4 + b) * 32 + nn];
        out[(size_t)(bb + b) * 32 + nn] = s;
    }
}

// ---------------------------------------------------------------------------
extern "C" void kernel_launch(void* const* d_in, const int* in_sizes, int n_in,
                              void* d_out, int out_size)
{
    const float* O    = (const float*)d_in[0];
    const float* Wenc = (const float*)d_in[1];
    const float* benc = (const float*)d_in[2];
    const float* W1   = (const float*)d_in[3];
    const float* b1   = (const float*)d_in[4];
    const float* W2   = (const float*)d_in[5];
    const float* b2   = (const float*)d_in[6];
    const float* W3   = (const float*)d_in[7];
    const float* b3   = (const float*)d_in[8];
    const float* W4   = (const float*)d_in[9];
    const float* b4   = (const float*)d_in[10];
    const float* Wdec = (const float*)d_in[11];
    const float* bdec = (const float*)d_in[12];
    float* out = (float*)d_out;

    cudaFuncSetAttribute(p1_compose,  cudaFuncAttributeMaxDynamicSharedMemorySize, 16960 * 4);
    cudaFuncSetAttribute(main_kernel, cudaFuncAttributeMaxDynamicSharedMemorySize, 42304 * 4);

    p0_wsum<<<8, 256>>>(Wdec);
    p1_compose<<<1, P1_TPB, 16960 * 4>>>(W1, b1, W2, b2, W3, b3, W4, b4, bdec);
    p2_buildM<<<64, 256>>>(Wdec);
    main_kernel<<<NBATCH / BPC, TPB, 42304 * 4>>>(O, Wenc, benc, out);
}